// round 1
// baseline (speedup 1.0000x reference)
#include <cuda_runtime.h>

#define NN 100000
#define EE 1600000
#define DD 128
#define RR 400
#define LN_EPS 1e-5f

// ---- scratch (static device globals; no allocations allowed) ----
__device__ float g_agg[(size_t)3 * NN * DD];   // per-bucket aggregated features (3,N,128)
__device__ int   g_cnt[3 * NN];                // per-bucket in-degree
__device__ float g_x1[(size_t)NN * DD];        // layer-1 output
__device__ float g_Wt[2][3 * DD * DD];         // relation weights, k-major [layer][r][d][o]
__device__ float g_Wst[2][DD * DD];            // self weights, k-major [layer][d][o]

// ---- transpose weights to k-major (once per call, tiny) ----
__global__ void transpose_w_kernel(const float* __restrict__ W1, const float* __restrict__ Ws1,
                                   const float* __restrict__ W2, const float* __restrict__ Ws2) {
    int idx = blockIdx.x * blockDim.x + threadIdx.x;   // 8 matrices * 16384
    if (idx >= 8 * DD * DD) return;
    int m = idx >> 14;
    int e = idx & (DD * DD - 1);
    int o = e >> 7;
    int d = e & 127;
    const float* src;
    float* dst;
    if (m < 3)       { src = W1 + m * DD * DD;       dst = g_Wt[0] + m * DD * DD; }
    else if (m == 3) { src = Ws1;                    dst = g_Wst[0]; }
    else if (m < 7)  { src = W2 + (m - 4) * DD * DD; dst = g_Wt[1] + (m - 4) * DD * DD; }
    else             { src = Ws2;                    dst = g_Wst[1]; }
    dst[d * DD + o] = src[o * DD + d];
}

// ---- zero agg (+ cnt on first pass) ----
__global__ void zero_agg_kernel(int zero_cnt_too) {
    size_t i = (size_t)blockIdx.x * blockDim.x + threadIdx.x;
    size_t stride = (size_t)gridDim.x * blockDim.x;
    float4* p = (float4*)g_agg;
    const size_t n4 = (size_t)3 * NN * DD / 4;
    float4 z = make_float4(0.f, 0.f, 0.f, 0.f);
    for (size_t k = i; k < n4; k += stride) p[k] = z;
    if (zero_cnt_too) {
        for (size_t k = i; k < (size_t)3 * NN; k += stride) g_cnt[k] = 0;
    }
}

// ---- per-bucket in-degree counts ----
__global__ void count_kernel(const int* __restrict__ edges) {
    int e = blockIdx.x * blockDim.x + threadIdx.x;
    if (e >= EE) return;
    int rel = edges[3 * e + 1];
    int dst = edges[3 * e + 2];
    int b = (rel >= RR) + (rel >= 2 * RR);
    atomicAdd(&g_cnt[b * NN + dst], 1);
}

// ---- edge scatter: warp per edge, float4 RED ----
__global__ void scatter_kernel(const int* __restrict__ edges, const float* __restrict__ node_emb,
                               int layer) {
    int gw = (blockIdx.x * blockDim.x + threadIdx.x) >> 5;
    int lane = threadIdx.x & 31;
    if (gw >= EE) return;
    const float* X = layer ? g_x1 : node_emb;
    int src = __ldg(&edges[3 * gw + 0]);
    int rel = __ldg(&edges[3 * gw + 1]);
    int dst = __ldg(&edges[3 * gw + 2]);
    int b = (rel >= RR) + (rel >= 2 * RR);
    float4 v = __ldg((const float4*)(X + (size_t)src * DD) + lane);
    atomicAdd(((float4*)(g_agg + ((size_t)b * NN + dst) * DD)) + lane, v);
}

// ---- fused transform: relation GEMM (K=384) -> relu((.+cnt*b)/deg) -> self GEMM (K=128)
//      -> +bs -> LayerNorm.  CTA: 128 threads, 64 nodes x 128 outs, 8x8 reg tile. ----
#define AS_STRIDE 68
#define BS_STRIDE 132

__global__ __launch_bounds__(128) void transform_kernel(
    const float* __restrict__ Xin,   // node_emb
    float* __restrict__ Out,         // final output buffer
    const float* __restrict__ b3,    // (3,128)
    const float* __restrict__ bs,    // (128)
    const float* __restrict__ gamma, // (128)
    const float* __restrict__ beta,  // (128)
    int layer) {
    __shared__ __align__(16) float As[32 * AS_STRIDE];
    __shared__ __align__(16) float Bs[32 * BS_STRIDE];

    const float* X   = layer ? g_x1 : Xin;
    float* outp      = layer ? Out  : g_x1;
    const float* Wt  = g_Wt[layer];
    const float* Wst = g_Wst[layer];

    const int tid = threadIdx.x;
    const int tx = tid & 15;     // out group: outs tx*8 .. tx*8+7
    const int ty = tid >> 4;     // node group: nodes ty*8 .. ty*8+7
    const int nodeBase = blockIdx.x * 64;

    float acc[8][8];
#pragma unroll
    for (int i = 0; i < 8; i++)
#pragma unroll
        for (int j = 0; j < 8; j++) acc[i][j] = 0.f;

    // ---------- phase 1: K = 384 over agg ----------
    for (int c = 0; c < 12; c++) {
        int r = c >> 2;
        int d0 = (c & 3) * 32;
        const float* Ap = g_agg + (size_t)r * NN * DD;
        const float* Bp = Wt + r * DD * DD;
#pragma unroll
        for (int t = 0; t < 4; t++) {
            int idx = tid + t * 128;          // 0..511
            int nl = idx >> 3, c4 = idx & 7;
            int n = nodeBase + nl; if (n >= NN) n = NN - 1;
            float4 v = __ldg((const float4*)(Ap + (size_t)n * DD + d0) + c4);
            int kk = c4 * 4;
            As[(kk + 0) * AS_STRIDE + nl] = v.x;
            As[(kk + 1) * AS_STRIDE + nl] = v.y;
            As[(kk + 2) * AS_STRIDE + nl] = v.z;
            As[(kk + 3) * AS_STRIDE + nl] = v.w;
        }
#pragma unroll
        for (int t = 0; t < 8; t++) {
            int idx = tid + t * 128;          // 0..1023
            int k = idx >> 5, o4 = idx & 31;
            float4 v = __ldg((const float4*)(Bp + (d0 + k) * DD) + o4);
            *(float4*)&Bs[k * BS_STRIDE + o4 * 4] = v;
        }
        __syncthreads();
#pragma unroll
        for (int k = 0; k < 32; k++) {
            float4 a0 = *(const float4*)&As[k * AS_STRIDE + ty * 8];
            float4 a1 = *(const float4*)&As[k * AS_STRIDE + ty * 8 + 4];
            float4 b0 = *(const float4*)&Bs[k * BS_STRIDE + tx * 8];
            float4 b1 = *(const float4*)&Bs[k * BS_STRIDE + tx * 8 + 4];
            float av[8] = {a0.x, a0.y, a0.z, a0.w, a1.x, a1.y, a1.z, a1.w};
            float bv[8] = {b0.x, b0.y, b0.z, b0.w, b1.x, b1.y, b1.z, b1.w};
#pragma unroll
            for (int i = 0; i < 8; i++)
#pragma unroll
                for (int j = 0; j < 8; j++) acc[i][j] += av[i] * bv[j];
        }
        __syncthreads();
    }

    // ---------- mid epilogue: bias*count, divide by degree, relu ----------
    float bb0[8], bb1[8], bb2[8];
#pragma unroll
    for (int j = 0; j < 8; j++) {
        bb0[j] = __ldg(&b3[tx * 8 + j]);
        bb1[j] = __ldg(&b3[DD + tx * 8 + j]);
        bb2[j] = __ldg(&b3[2 * DD + tx * 8 + j]);
    }
#pragma unroll
    for (int i = 0; i < 8; i++) {
        int n = nodeBase + ty * 8 + i; if (n >= NN) n = NN - 1;
        float c0 = (float)__ldg(&g_cnt[n]);
        float c1 = (float)__ldg(&g_cnt[NN + n]);
        float c2 = (float)__ldg(&g_cnt[2 * NN + n]);
        float inv = 1.0f / fmaxf(c0 + c1 + c2, 1.0f);
#pragma unroll
        for (int j = 0; j < 8; j++) {
            float v = (acc[i][j] + c0 * bb0[j] + c1 * bb1[j] + c2 * bb2[j]) * inv;
            acc[i][j] = fmaxf(v, 0.0f);
        }
    }

    // ---------- phase 2: K = 128 self loop ----------
    for (int c = 0; c < 4; c++) {
        int d0 = c * 32;
#pragma unroll
        for (int t = 0; t < 4; t++) {
            int idx = tid + t * 128;
            int nl = idx >> 3, c4 = idx & 7;
            int n = nodeBase + nl; if (n >= NN) n = NN - 1;
            float4 v = __ldg((const float4*)(X + (size_t)n * DD + d0) + c4);
            int kk = c4 * 4;
            As[(kk + 0) * AS_STRIDE + nl] = v.x;
            As[(kk + 1) * AS_STRIDE + nl] = v.y;
            As[(kk + 2) * AS_STRIDE + nl] = v.z;
            As[(kk + 3) * AS_STRIDE + nl] = v.w;
        }
#pragma unroll
        for (int t = 0; t < 8; t++) {
            int idx = tid + t * 128;
            int k = idx >> 5, o4 = idx & 31;
            float4 v = __ldg((const float4*)(Wst + (d0 + k) * DD) + o4);
            *(float4*)&Bs[k * BS_STRIDE + o4 * 4] = v;
        }
        __syncthreads();
#pragma unroll
        for (int k = 0; k < 32; k++) {
            float4 a0 = *(const float4*)&As[k * AS_STRIDE + ty * 8];
            float4 a1 = *(const float4*)&As[k * AS_STRIDE + ty * 8 + 4];
            float4 b0 = *(const float4*)&Bs[k * BS_STRIDE + tx * 8];
            float4 b1 = *(const float4*)&Bs[k * BS_STRIDE + tx * 8 + 4];
            float av[8] = {a0.x, a0.y, a0.z, a0.w, a1.x, a1.y, a1.z, a1.w};
            float bv[8] = {b0.x, b0.y, b0.z, b0.w, b1.x, b1.y, b1.z, b1.w};
#pragma unroll
            for (int i = 0; i < 8; i++)
#pragma unroll
                for (int j = 0; j < 8; j++) acc[i][j] += av[i] * bv[j];
        }
        __syncthreads();
    }

    // ---------- final epilogue: +bs, LayerNorm over 128 outs ----------
    float bsv[8], gv[8], bev[8];
#pragma unroll
    for (int j = 0; j < 8; j++) {
        bsv[j] = __ldg(&bs[tx * 8 + j]);
        gv[j]  = __ldg(&gamma[tx * 8 + j]);
        bev[j] = __ldg(&beta[tx * 8 + j]);
    }
#pragma unroll
    for (int i = 0; i < 8; i++) {
#pragma unroll
        for (int j = 0; j < 8; j++) acc[i][j] += bsv[j];
        float s = 0.f, s2 = 0.f;
#pragma unroll
        for (int j = 0; j < 8; j++) { s += acc[i][j]; s2 += acc[i][j] * acc[i][j]; }
        // reduce across the 16 tx-lanes (xor offsets stay within each 16-lane half)
#pragma unroll
        for (int off = 8; off >= 1; off >>= 1) {
            s  += __shfl_xor_sync(0xffffffffu, s,  off);
            s2 += __shfl_xor_sync(0xffffffffu, s2, off);
        }
        float mean = s * (1.0f / 128.0f);
        float var  = s2 * (1.0f / 128.0f) - mean * mean;
        float rstd = rsqrtf(var + LN_EPS);
        int n = nodeBase + ty * 8 + i;
        if (n < NN) {
            float4 o0, o1;
            o0.x = (acc[i][0] - mean) * rstd * gv[0] + bev[0];
            o0.y = (acc[i][1] - mean) * rstd * gv[1] + bev[1];
            o0.z = (acc[i][2] - mean) * rstd * gv[2] + bev[2];
            o0.w = (acc[i][3] - mean) * rstd * gv[3] + bev[3];
            o1.x = (acc[i][4] - mean) * rstd * gv[4] + bev[4];
            o1.y = (acc[i][5] - mean) * rstd * gv[5] + bev[5];
            o1.z = (acc[i][6] - mean) * rstd * gv[6] + bev[6];
            o1.w = (acc[i][7] - mean) * rstd * gv[7] + bev[7];
            *(float4*)(outp + (size_t)n * DD + tx * 8)     = o0;
            *(float4*)(outp + (size_t)n * DD + tx * 8 + 4) = o1;
        }
    }
}

extern "C" void kernel_launch(void* const* d_in, const int* in_sizes, int n_in,
                              void* d_out, int out_size) {
    const int*   edges    = (const int*)d_in[0];
    const float* node_emb = (const float*)d_in[1];
    const float* W1  = (const float*)d_in[2];
    const float* b1  = (const float*)d_in[3];
    const float* Ws1 = (const float*)d_in[4];
    const float* bs1 = (const float*)d_in[5];
    const float* g1  = (const float*)d_in[6];
    const float* be1 = (const float*)d_in[7];
    const float* W2  = (const float*)d_in[8];
    const float* b2  = (const float*)d_in[9];
    const float* Ws2 = (const float*)d_in[10];
    const float* bs2 = (const float*)d_in[11];
    const float* g2  = (const float*)d_in[12];
    const float* be2 = (const float*)d_in[13];
    float* out = (float*)d_out;

    transpose_w_kernel<<<(8 * DD * DD + 255) / 256, 256>>>(W1, Ws1, W2, Ws2);
    zero_agg_kernel<<<2368, 256>>>(1);
    count_kernel<<<(EE + 255) / 256, 256>>>(edges);
    scatter_kernel<<<EE * 32 / 256, 256>>>(edges, node_emb, 0);
    transform_kernel<<<(NN + 63) / 64, 128>>>(node_emb, out, b1, bs1, g1, be1, 0);
    zero_agg_kernel<<<2368, 256>>>(0);
    scatter_kernel<<<EE * 32 / 256, 256>>>(edges, node_emb, 1);
    transform_kernel<<<(NN + 63) / 64, 128>>>(node_emb, out, b2, bs2, g2, be2, 1);
}

// round 3
// speedup vs baseline: 1.3225x; 1.3225x over previous
#include <cuda_runtime.h>

#define NN 100000
#define EE 1600000
#define DD 128
#define RR 400
#define LN_EPS 1e-5f
#define ASTR 137          // As smem stride (scalar access only; odd => conflict-free transpose)
#define BSTR 136          // Bs smem stride (mult of 4 => aligned float4 stores; 8 mod 32 => conflict-free loads)

// ---- scratch (static device globals; no allocations allowed) ----
__device__ float g_agg[(size_t)3 * NN * DD];   // per-bucket aggregated features (3,N,128)
__device__ int   g_cnt[3 * NN];                // per-bucket in-degree
__device__ float g_x1[(size_t)NN * DD];        // layer-1 output
__device__ float g_Wt[2][3 * DD * DD];         // relation weights, k-major, tf32-rounded
__device__ float g_Wst[2][DD * DD];            // self weights, k-major, tf32-rounded
__device__ int2  g_elist[(size_t)3 * EE];      // bucket-sorted (src,dst) lists
__device__ int   g_elen[3];

__device__ __forceinline__ float to_tf32(float x) {
    unsigned u;
    asm("cvt.rna.tf32.f32 %0, %1;" : "=r"(u) : "f"(x));
    return __uint_as_float(u);
}

__device__ __forceinline__ void mma_tf32(float* c, const unsigned* a, unsigned b0, unsigned b1) {
    asm volatile(
        "mma.sync.aligned.m16n8k8.row.col.f32.tf32.tf32.f32 "
        "{%0,%1,%2,%3},{%4,%5,%6,%7},{%8,%9},{%0,%1,%2,%3};\n"
        : "+f"(c[0]), "+f"(c[1]), "+f"(c[2]), "+f"(c[3])
        : "r"(a[0]), "r"(a[1]), "r"(a[2]), "r"(a[3]), "r"(b0), "r"(b1));
}

// ---- transpose weights to k-major + tf32 round; zero g_elen ----
__global__ void transpose_w_kernel(const float* __restrict__ W1, const float* __restrict__ Ws1,
                                   const float* __restrict__ W2, const float* __restrict__ Ws2) {
    int idx = blockIdx.x * blockDim.x + threadIdx.x;   // 8 matrices * 16384
    if (idx < 3) g_elen[idx] = 0;
    if (idx >= 8 * DD * DD) return;
    int m = idx >> 14;
    int e = idx & (DD * DD - 1);
    int o = e >> 7;
    int d = e & 127;
    const float* src;
    float* dst;
    if (m < 3)       { src = W1 + m * DD * DD;       dst = g_Wt[0] + m * DD * DD; }
    else if (m == 3) { src = Ws1;                    dst = g_Wst[0]; }
    else if (m < 7)  { src = W2 + (m - 4) * DD * DD; dst = g_Wt[1] + (m - 4) * DD * DD; }
    else             { src = Ws2;                    dst = g_Wst[1]; }
    dst[d * DD + o] = to_tf32(src[o * DD + d]);
}

// ---- build bucket-sorted edge lists (block-aggregated global atomics) ----
__global__ void build_lists_kernel(const int* __restrict__ edges) {
    __shared__ int s_cnt[3];
    __shared__ int s_base[3];
    int tid = threadIdx.x;
    if (tid < 3) s_cnt[tid] = 0;
    __syncthreads();
    int e = blockIdx.x * blockDim.x + tid;
    int b = 0, rank = 0, src = 0, dst = 0;
    bool valid = e < EE;
    if (valid) {
        src = edges[3 * e + 0];
        int rel = edges[3 * e + 1];
        dst = edges[3 * e + 2];
        b = (rel >= RR) + (rel >= 2 * RR);
        rank = atomicAdd(&s_cnt[b], 1);
    }
    __syncthreads();
    if (tid < 3) s_base[tid] = atomicAdd(&g_elen[tid], s_cnt[tid]);
    __syncthreads();
    if (valid) g_elist[(size_t)b * EE + s_base[b] + rank] = make_int2(src, dst);
}

// ---- zero agg (+ cnt on first pass) ----
__global__ void zero_agg_kernel(int zero_cnt_too) {
    size_t i = (size_t)blockIdx.x * blockDim.x + threadIdx.x;
    size_t stride = (size_t)gridDim.x * blockDim.x;
    float4* p = (float4*)g_agg;
    const size_t n4 = (size_t)3 * NN * DD / 4;
    float4 z = make_float4(0.f, 0.f, 0.f, 0.f);
    for (size_t k = i; k < n4; k += stride) p[k] = z;
    if (zero_cnt_too) {
        for (size_t k = i; k < (size_t)3 * NN; k += stride) g_cnt[k] = 0;
    }
}

// ---- per-bucket in-degree counts ----
__global__ void count_kernel(const int* __restrict__ edges) {
    int e = blockIdx.x * blockDim.x + threadIdx.x;
    if (e >= EE) return;
    int rel = edges[3 * e + 1];
    int dst = edges[3 * e + 2];
    int b = (rel >= RR) + (rel >= 2 * RR);
    atomicAdd(&g_cnt[b * NN + dst], 1);
}

// ---- edge scatter over bucket-sorted lists: warp per edge, float4 RED.
//      Bucket-ordered traversal keeps (agg_bucket + x) L2-resident. ----
__global__ void scatter_kernel(const float* __restrict__ node_emb, int layer) {
    int gw = (blockIdx.x * blockDim.x + threadIdx.x) >> 5;
    int lane = threadIdx.x & 31;
    if (gw >= EE) return;
    int l0 = __ldg(&g_elen[0]);
    int l1 = __ldg(&g_elen[1]);
    int b, idx;
    if (gw < l0)           { b = 0; idx = gw; }
    else if (gw < l0 + l1) { b = 1; idx = gw - l0; }
    else                   { b = 2; idx = gw - l0 - l1; }
    int2 sd = __ldg(&g_elist[(size_t)b * EE + idx]);
    const float* X = layer ? g_x1 : node_emb;
    float4 v = __ldg((const float4*)(X + (size_t)sd.x * DD) + lane);
    atomicAdd(((float4*)(g_agg + ((size_t)b * NN + sd.y) * DD)) + lane, v);
}

// ---- fused transform on tensor cores (tf32 mma.sync m16n8k8):
//      relation GEMM (K=384) -> relu((.+cnt*b)/deg) -> self GEMM (K=128)
//      -> +bs -> LayerNorm.  CTA: 256 threads, 128 nodes x 128 outs. ----
__global__ __launch_bounds__(256) void transform_kernel(
    const float* __restrict__ Xin,   // node_emb
    float* __restrict__ Out,         // final output buffer
    const float* __restrict__ b3,    // (3,128)
    const float* __restrict__ bs,    // (128)
    const float* __restrict__ gamma, // (128)
    const float* __restrict__ beta,  // (128)
    int layer) {
    __shared__ float As[32 * ASTR];                  // [k][node], scalar access
    __shared__ __align__(16) float Bs[32 * BSTR];    // [k][out], float4 stores
    __shared__ float Sred[2][128][2];                // cross-warp LN partials

    const float* X   = layer ? g_x1 : Xin;
    float* outp      = layer ? Out  : g_x1;
    const float* Wt  = g_Wt[layer];
    const float* Wst = g_Wst[layer];

    const int tid = threadIdx.x;
    const int lane = tid & 31;
    const int wid = tid >> 5;
    const int warp_m = wid & 3;    // node block of 32
    const int warp_n = wid >> 2;   // out block of 64
    const int grp = lane >> 2;     // 0..7
    const int tid4 = lane & 3;     // 0..3
    const int nodeBase = blockIdx.x * 128;

    float acc[2][8][4];
#pragma unroll
    for (int mt = 0; mt < 2; mt++)
#pragma unroll
        for (int t = 0; t < 8; t++)
#pragma unroll
            for (int q = 0; q < 4; q++) acc[mt][t][q] = 0.f;

    // ================= phase 1: K = 384 over agg =================
    for (int c = 0; c < 12; c++) {
        int r = c >> 2;
        int d0 = (c & 3) * 32;
        const float* Ap = g_agg + (size_t)r * NN * DD;
        const float* Bp = Wt + r * DD * DD;
        // load A chunk: 128 nodes x 32 k, transposed to [k][node], tf32-rounded
#pragma unroll
        for (int t = 0; t < 4; t++) {
            int idx = tid + t * 256;           // 0..1023
            int nl = idx >> 3;                 // node 0..127
            int c4 = idx & 7;                  // float4 col 0..7
            int n = nodeBase + nl; if (n >= NN) n = NN - 1;
            float4 v = __ldg((const float4*)(Ap + (size_t)n * DD + d0) + c4);
            int kk = c4 * 4;
            As[(kk + 0) * ASTR + nl] = to_tf32(v.x);
            As[(kk + 1) * ASTR + nl] = to_tf32(v.y);
            As[(kk + 2) * ASTR + nl] = to_tf32(v.z);
            As[(kk + 3) * ASTR + nl] = to_tf32(v.w);
        }
        // load B chunk: 32 k x 128 outs (already tf32)
#pragma unroll
        for (int t = 0; t < 4; t++) {
            int idx = tid + t * 256;
            int k = idx >> 5, o4 = idx & 31;
            float4 v = __ldg((const float4*)(Bp + (d0 + k) * DD) + o4);
            *(float4*)&Bs[k * BSTR + o4 * 4] = v;
        }
        __syncthreads();
#pragma unroll
        for (int ks = 0; ks < 4; ks++) {
            int k0 = ks * 8;
            unsigned a[2][4];
#pragma unroll
            for (int mt = 0; mt < 2; mt++) {
                int mrow = warp_m * 32 + mt * 16 + grp;
                a[mt][0] = __float_as_uint(As[(k0 + tid4) * ASTR + mrow]);
                a[mt][1] = __float_as_uint(As[(k0 + tid4) * ASTR + mrow + 8]);
                a[mt][2] = __float_as_uint(As[(k0 + tid4 + 4) * ASTR + mrow]);
                a[mt][3] = __float_as_uint(As[(k0 + tid4 + 4) * ASTR + mrow + 8]);
            }
#pragma unroll
            for (int t = 0; t < 8; t++) {
                int oc = warp_n * 64 + t * 8 + grp;
                unsigned b0 = __float_as_uint(Bs[(k0 + tid4) * BSTR + oc]);
                unsigned b1 = __float_as_uint(Bs[(k0 + tid4 + 4) * BSTR + oc]);
                mma_tf32(acc[0][t], a[0], b0, b1);
                mma_tf32(acc[1][t], a[1], b0, b1);
            }
        }
        __syncthreads();
    }

    // ---------- mid epilogue: +cnt*bias, /degree, relu ----------
#pragma unroll
    for (int mt = 0; mt < 2; mt++) {
#pragma unroll
        for (int rr = 0; rr < 2; rr++) {
            int n = nodeBase + warp_m * 32 + mt * 16 + grp + rr * 8;
            if (n >= NN) n = NN - 1;
            float c0 = (float)__ldg(&g_cnt[n]);
            float c1 = (float)__ldg(&g_cnt[NN + n]);
            float c2 = (float)__ldg(&g_cnt[2 * NN + n]);
            float inv = 1.0f / fmaxf(c0 + c1 + c2, 1.0f);
#pragma unroll
            for (int t = 0; t < 8; t++) {
#pragma unroll
                for (int q = 0; q < 2; q++) {
                    int col = warp_n * 64 + t * 8 + 2 * tid4 + q;
                    int ci = rr * 2 + q;
                    float v = acc[mt][t][ci] + c0 * __ldg(&b3[col])
                            + c1 * __ldg(&b3[DD + col]) + c2 * __ldg(&b3[2 * DD + col]);
                    acc[mt][t][ci] = fmaxf(v * inv, 0.0f);
                }
            }
        }
    }

    // ================= phase 2: K = 128 self loop =================
    for (int c = 0; c < 4; c++) {
        int d0 = c * 32;
#pragma unroll
        for (int t = 0; t < 4; t++) {
            int idx = tid + t * 256;
            int nl = idx >> 3, c4 = idx & 7;
            int n = nodeBase + nl; if (n >= NN) n = NN - 1;
            float4 v = __ldg((const float4*)(X + (size_t)n * DD + d0) + c4);
            int kk = c4 * 4;
            As[(kk + 0) * ASTR + nl] = to_tf32(v.x);
            As[(kk + 1) * ASTR + nl] = to_tf32(v.y);
            As[(kk + 2) * ASTR + nl] = to_tf32(v.z);
            As[(kk + 3) * ASTR + nl] = to_tf32(v.w);
        }
#pragma unroll
        for (int t = 0; t < 4; t++) {
            int idx = tid + t * 256;
            int k = idx >> 5, o4 = idx & 31;
            float4 v = __ldg((const float4*)(Wst + (d0 + k) * DD) + o4);
            *(float4*)&Bs[k * BSTR + o4 * 4] = v;
        }
        __syncthreads();
#pragma unroll
        for (int ks = 0; ks < 4; ks++) {
            int k0 = ks * 8;
            unsigned a[2][4];
#pragma unroll
            for (int mt = 0; mt < 2; mt++) {
                int mrow = warp_m * 32 + mt * 16 + grp;
                a[mt][0] = __float_as_uint(As[(k0 + tid4) * ASTR + mrow]);
                a[mt][1] = __float_as_uint(As[(k0 + tid4) * ASTR + mrow + 8]);
                a[mt][2] = __float_as_uint(As[(k0 + tid4 + 4) * ASTR + mrow]);
                a[mt][3] = __float_as_uint(As[(k0 + tid4 + 4) * ASTR + mrow + 8]);
            }
#pragma unroll
            for (int t = 0; t < 8; t++) {
                int oc = warp_n * 64 + t * 8 + grp;
                unsigned b0 = __float_as_uint(Bs[(k0 + tid4) * BSTR + oc]);
                unsigned b1 = __float_as_uint(Bs[(k0 + tid4 + 4) * BSTR + oc]);
                mma_tf32(acc[0][t], a[0], b0, b1);
                mma_tf32(acc[1][t], a[1], b0, b1);
            }
        }
        __syncthreads();
    }

    // ---------- final epilogue: +bs, LayerNorm over 128 outs ----------
    float ps[2][2], ps2[2][2];
#pragma unroll
    for (int mt = 0; mt < 2; mt++) {
#pragma unroll
        for (int rr = 0; rr < 2; rr++) {
            float s = 0.f, s2 = 0.f;
#pragma unroll
            for (int t = 0; t < 8; t++) {
#pragma unroll
                for (int q = 0; q < 2; q++) {
                    int col = warp_n * 64 + t * 8 + 2 * tid4 + q;
                    int ci = rr * 2 + q;
                    float v = acc[mt][t][ci] + __ldg(&bs[col]);
                    acc[mt][t][ci] = v;
                    s += v; s2 += v * v;
                }
            }
            // reduce across the 4 tid4 lanes (grp preserved)
            s  += __shfl_xor_sync(0xffffffffu, s, 1);
            s2 += __shfl_xor_sync(0xffffffffu, s2, 1);
            s  += __shfl_xor_sync(0xffffffffu, s, 2);
            s2 += __shfl_xor_sync(0xffffffffu, s2, 2);
            ps[mt][rr] = s; ps2[mt][rr] = s2;
            if (tid4 == 0) {
                int ln = warp_m * 32 + mt * 16 + grp + rr * 8;
                Sred[warp_n][ln][0] = s;
                Sred[warp_n][ln][1] = s2;
            }
        }
    }
    __syncthreads();
#pragma unroll
    for (int mt = 0; mt < 2; mt++) {
#pragma unroll
        for (int rr = 0; rr < 2; rr++) {
            int ln = warp_m * 32 + mt * 16 + grp + rr * 8;
            float s  = ps[mt][rr]  + Sred[1 - warp_n][ln][0];
            float s2 = ps2[mt][rr] + Sred[1 - warp_n][ln][1];
            float mean = s * (1.0f / 128.0f);
            float var  = s2 * (1.0f / 128.0f) - mean * mean;
            float rstd = rsqrtf(var + LN_EPS);
            int n = nodeBase + ln;
            if (n < NN) {
#pragma unroll
                for (int t = 0; t < 8; t++) {
                    int col = warp_n * 64 + t * 8 + 2 * tid4;
                    float2 o;
                    o.x = (acc[mt][t][rr * 2 + 0] - mean) * rstd * __ldg(&gamma[col]) + __ldg(&beta[col]);
                    o.y = (acc[mt][t][rr * 2 + 1] - mean) * rstd * __ldg(&gamma[col + 1]) + __ldg(&beta[col + 1]);
                    *(float2*)(outp + (size_t)n * DD + col) = o;
                }
            }
        }
    }
}

extern "C" void kernel_launch(void* const* d_in, const int* in_sizes, int n_in,
                              void* d_out, int out_size) {
    const int*   edges    = (const int*)d_in[0];
    const float* node_emb = (const float*)d_in[1];
    const float* W1  = (const float*)d_in[2];
    const float* b1  = (const float*)d_in[3];
    const float* Ws1 = (const float*)d_in[4];
    const float* bs1 = (const float*)d_in[5];
    const float* g1  = (const float*)d_in[6];
    const float* be1 = (const float*)d_in[7];
    const float* W2  = (const float*)d_in[8];
    const float* b2  = (const float*)d_in[9];
    const float* Ws2 = (const float*)d_in[10];
    const float* bs2 = (const float*)d_in[11];
    const float* g2  = (const float*)d_in[12];
    const float* be2 = (const float*)d_in[13];
    float* out = (float*)d_out;

    transpose_w_kernel<<<(8 * DD * DD + 255) / 256, 256>>>(W1, Ws1, W2, Ws2);
    build_lists_kernel<<<(EE + 255) / 256, 256>>>(edges);
    zero_agg_kernel<<<2368, 256>>>(1);
    count_kernel<<<(EE + 255) / 256, 256>>>(edges);
    scatter_kernel<<<EE * 32 / 256, 256>>>(node_emb, 0);
    transform_kernel<<<(NN + 127) / 128, 256>>>(node_emb, out, b1, bs1, g1, be1, 0);
    zero_agg_kernel<<<2368, 256>>>(0);
    scatter_kernel<<<EE * 32 / 256, 256>>>(node_emb, 1);
    transform_kernel<<<(NN + 127) / 128, 256>>>(node_emb, out, b2, bs2, g2, be2, 1);
}

// round 4
// speedup vs baseline: 1.8376x; 1.3896x over previous
#include <cuda_runtime.h>

#define NN 100000
#define EE 1600000
#define TN (3 * NN)
#define DD 128
#define RR 400
#define LN_EPS 1e-5f
#define ASTR 137          // As smem stride (scalar access only; odd => conflict-free transpose)
#define BSTR 136          // Bs smem stride (mult of 4 => aligned float4 stores; conflict-free loads)
#define SCAN_BLK 4096     // elements per scan1 block (256 threads x 16)
#define NBLK ((TN + SCAN_BLK - 1) / SCAN_BLK)   // 74

// ---- scratch (static device globals; no allocations allowed) ----
__device__ float g_agg[(size_t)3 * NN * DD];   // per-bucket aggregated features (3,N,128)
__device__ int   g_cnt[TN];                    // per-(bucket,dst) in-degree
__device__ int   g_rowptr[TN];                 // CSR row pointers (exclusive prefix of g_cnt)
__device__ int   g_cur[TN];                    // fill cursors
__device__ int   g_blk[128];                   // scan block totals
__device__ int   g_eidx[EE];                   // src index array, sorted by (bucket,dst)
__device__ float g_x1[(size_t)NN * DD];        // layer-1 output
__device__ float g_Wt[2][3 * DD * DD];         // relation weights, k-major, tf32-rounded
__device__ float g_Wst[2][DD * DD];            // self weights, k-major, tf32-rounded

__device__ __forceinline__ float to_tf32(float x) {
    unsigned u;
    asm("cvt.rna.tf32.f32 %0, %1;" : "=r"(u) : "f"(x));
    return __uint_as_float(u);
}

__device__ __forceinline__ void mma_tf32(float* c, const unsigned* a, unsigned b0, unsigned b1) {
    asm volatile(
        "mma.sync.aligned.m16n8k8.row.col.f32.tf32.tf32.f32 "
        "{%0,%1,%2,%3},{%4,%5,%6,%7},{%8,%9},{%0,%1,%2,%3};\n"
        : "+f"(c[0]), "+f"(c[1]), "+f"(c[2]), "+f"(c[3])
        : "r"(a[0]), "r"(a[1]), "r"(a[2]), "r"(a[3]), "r"(b0), "r"(b1));
}

// ---- transpose weights to k-major + tf32 round ----
__global__ void transpose_w_kernel(const float* __restrict__ W1, const float* __restrict__ Ws1,
                                   const float* __restrict__ W2, const float* __restrict__ Ws2) {
    int idx = blockIdx.x * blockDim.x + threadIdx.x;   // 8 matrices * 16384
    if (idx >= 8 * DD * DD) return;
    int m = idx >> 14;
    int e = idx & (DD * DD - 1);
    int o = e >> 7;
    int d = e & 127;
    const float* src;
    float* dst;
    if (m < 3)       { src = W1 + m * DD * DD;       dst = g_Wt[0] + m * DD * DD; }
    else if (m == 3) { src = Ws1;                    dst = g_Wst[0]; }
    else if (m < 7)  { src = W2 + (m - 4) * DD * DD; dst = g_Wt[1] + (m - 4) * DD * DD; }
    else             { src = Ws2;                    dst = g_Wst[1]; }
    dst[d * DD + o] = to_tf32(src[o * DD + d]);
}

// ---- per-(bucket,dst) in-degree counts ----
__global__ void count_kernel(const int* __restrict__ edges) {
    int e = blockIdx.x * blockDim.x + threadIdx.x;
    if (e >= EE) return;
    int rel = edges[3 * e + 1];
    int dst = edges[3 * e + 2];
    int b = (rel >= RR) + (rel >= 2 * RR);
    atomicAdd(&g_cnt[b * NN + dst], 1);
}

// ---- exclusive scan pass 1: per-block local scan + block totals ----
__global__ __launch_bounds__(256) void scan1_kernel() {
    __shared__ int sm[256];
    int tid = threadIdx.x;
    int base = blockIdx.x * SCAN_BLK + tid * 16;
    int c[16];
    int run = 0;
#pragma unroll
    for (int t = 0; t < 16; t++) {
        int v = (base + t < TN) ? g_cnt[base + t] : 0;
        c[t] = run;
        run += v;
    }
    sm[tid] = run;
    __syncthreads();
    // inclusive Hillis-Steele scan of thread totals
    for (int d = 1; d < 256; d <<= 1) {
        int v = (tid >= d) ? sm[tid - d] : 0;
        __syncthreads();
        sm[tid] += v;
        __syncthreads();
    }
    int texcl = sm[tid] - run;
#pragma unroll
    for (int t = 0; t < 16; t++)
        if (base + t < TN) g_rowptr[base + t] = texcl + c[t];
    if (tid == 255) g_blk[blockIdx.x] = sm[255];
}

// ---- scan pass 2: exclusive scan of block totals (single block) ----
__global__ __launch_bounds__(128) void scan2_kernel() {
    __shared__ int sm[128];
    int tid = threadIdx.x;
    int v = (tid < NBLK) ? g_blk[tid] : 0;
    sm[tid] = v;
    __syncthreads();
    for (int d = 1; d < 128; d <<= 1) {
        int u = (tid >= d) ? sm[tid - d] : 0;
        __syncthreads();
        sm[tid] += u;
        __syncthreads();
    }
    if (tid < NBLK) g_blk[tid] = sm[tid] - v;   // exclusive
}

// ---- scan pass 3: add block offsets, init cursors ----
__global__ void scan3_kernel() {
    int idx = blockIdx.x * blockDim.x + threadIdx.x;
    if (idx >= TN) return;
    int v = g_rowptr[idx] + g_blk[idx / SCAN_BLK];
    g_rowptr[idx] = v;
    g_cur[idx] = v;
}

// ---- fill CSR: place src of each edge into its (bucket,dst) segment ----
__global__ void fill_kernel(const int* __restrict__ edges) {
    int e = blockIdx.x * blockDim.x + threadIdx.x;
    if (e >= EE) return;
    int src = edges[3 * e + 0];
    int rel = edges[3 * e + 1];
    int dst = edges[3 * e + 2];
    int b = (rel >= RR) + (rel >= 2 * RR);
    int pos = atomicAdd(&g_cur[b * NN + dst], 1);
    g_eidx[pos] = src;
}

// ---- gather: warp per (bucket,dst) segment; pure reads + one store.
//      Bucket-major order keeps x L2-resident. Replaces zero+atomic scatter. ----
__global__ void gather_kernel(const float* __restrict__ node_emb, int layer) {
    int gw = (blockIdx.x * blockDim.x + threadIdx.x) >> 5;
    int lane = threadIdx.x & 31;
    if (gw >= TN) return;
    const float* X = layer ? g_x1 : node_emb;
    int s = __ldg(&g_rowptr[gw]);
    int e = (gw + 1 < TN) ? __ldg(&g_rowptr[gw + 1]) : EE;
    float4 a0 = make_float4(0.f, 0.f, 0.f, 0.f);
    float4 a1 = make_float4(0.f, 0.f, 0.f, 0.f);
    int j = s;
    for (; j + 2 <= e; j += 2) {
        int s0 = __ldg(&g_eidx[j]);
        int s1 = __ldg(&g_eidx[j + 1]);
        float4 v0 = __ldg((const float4*)(X + (size_t)s0 * DD) + lane);
        float4 v1 = __ldg((const float4*)(X + (size_t)s1 * DD) + lane);
        a0.x += v0.x; a0.y += v0.y; a0.z += v0.z; a0.w += v0.w;
        a1.x += v1.x; a1.y += v1.y; a1.z += v1.z; a1.w += v1.w;
    }
    if (j < e) {
        int s0 = __ldg(&g_eidx[j]);
        float4 v0 = __ldg((const float4*)(X + (size_t)s0 * DD) + lane);
        a0.x += v0.x; a0.y += v0.y; a0.z += v0.z; a0.w += v0.w;
    }
    float4 r = make_float4(a0.x + a1.x, a0.y + a1.y, a0.z + a1.z, a0.w + a1.w);
    *((float4*)(g_agg + (size_t)gw * DD) + lane) = r;
}

// ---- fused transform on tensor cores (tf32 mma.sync m16n8k8):
//      relation GEMM (K=384) -> relu((.+cnt*b)/deg) -> self GEMM (K=128)
//      -> +bs -> LayerNorm.  CTA: 256 threads, 128 nodes x 128 outs. ----
__global__ __launch_bounds__(256) void transform_kernel(
    const float* __restrict__ Xin,   // node_emb
    float* __restrict__ Out,         // final output buffer
    const float* __restrict__ b3,    // (3,128)
    const float* __restrict__ bs,    // (128)
    const float* __restrict__ gamma, // (128)
    const float* __restrict__ beta,  // (128)
    int layer) {
    __shared__ float As[32 * ASTR];                  // [k][node], scalar access
    __shared__ __align__(16) float Bs[32 * BSTR];    // [k][out], float4 stores
    __shared__ float Sred[2][128][2];                // cross-warp LN partials

    const float* X   = layer ? g_x1 : Xin;
    float* outp      = layer ? Out  : g_x1;
    const float* Wt  = g_Wt[layer];
    const float* Wst = g_Wst[layer];

    const int tid = threadIdx.x;
    const int lane = tid & 31;
    const int wid = tid >> 5;
    const int warp_m = wid & 3;    // node block of 32
    const int warp_n = wid >> 2;   // out block of 64
    const int grp = lane >> 2;     // 0..7
    const int tid4 = lane & 3;     // 0..3
    const int nodeBase = blockIdx.x * 128;

    float acc[2][8][4];
#pragma unroll
    for (int mt = 0; mt < 2; mt++)
#pragma unroll
        for (int t = 0; t < 8; t++)
#pragma unroll
            for (int q = 0; q < 4; q++) acc[mt][t][q] = 0.f;

    // ================= phase 1: K = 384 over agg =================
    for (int c = 0; c < 12; c++) {
        int r = c >> 2;
        int d0 = (c & 3) * 32;
        const float* Ap = g_agg + (size_t)r * NN * DD;
        const float* Bp = Wt + r * DD * DD;
        // load A chunk: 128 nodes x 32 k, transposed to [k][node], tf32-rounded
#pragma unroll
        for (int t = 0; t < 4; t++) {
            int idx = tid + t * 256;           // 0..1023
            int nl = idx >> 3;                 // node 0..127
            int c4 = idx & 7;                  // float4 col 0..7
            int n = nodeBase + nl; if (n >= NN) n = NN - 1;
            float4 v = __ldg((const float4*)(Ap + (size_t)n * DD + d0) + c4);
            int kk = c4 * 4;
            As[(kk + 0) * ASTR + nl] = to_tf32(v.x);
            As[(kk + 1) * ASTR + nl] = to_tf32(v.y);
            As[(kk + 2) * ASTR + nl] = to_tf32(v.z);
            As[(kk + 3) * ASTR + nl] = to_tf32(v.w);
        }
        // load B chunk: 32 k x 128 outs (already tf32)
#pragma unroll
        for (int t = 0; t < 4; t++) {
            int idx = tid + t * 256;
            int k = idx >> 5, o4 = idx & 31;
            float4 v = __ldg((const float4*)(Bp + (d0 + k) * DD) + o4);
            *(float4*)&Bs[k * BSTR + o4 * 4] = v;
        }
        __syncthreads();
#pragma unroll
        for (int ks = 0; ks < 4; ks++) {
            int k0 = ks * 8;
            unsigned a[2][4];
#pragma unroll
            for (int mt = 0; mt < 2; mt++) {
                int mrow = warp_m * 32 + mt * 16 + grp;
                a[mt][0] = __float_as_uint(As[(k0 + tid4) * ASTR + mrow]);
                a[mt][1] = __float_as_uint(As[(k0 + tid4) * ASTR + mrow + 8]);
                a[mt][2] = __float_as_uint(As[(k0 + tid4 + 4) * ASTR + mrow]);
                a[mt][3] = __float_as_uint(As[(k0 + tid4 + 4) * ASTR + mrow + 8]);
            }
#pragma unroll
            for (int t = 0; t < 8; t++) {
                int oc = warp_n * 64 + t * 8 + grp;
                unsigned b0 = __float_as_uint(Bs[(k0 + tid4) * BSTR + oc]);
                unsigned b1 = __float_as_uint(Bs[(k0 + tid4 + 4) * BSTR + oc]);
                mma_tf32(acc[0][t], a[0], b0, b1);
                mma_tf32(acc[1][t], a[1], b0, b1);
            }
        }
        __syncthreads();
    }

    // ---------- mid epilogue: +cnt*bias, /degree, relu ----------
#pragma unroll
    for (int mt = 0; mt < 2; mt++) {
#pragma unroll
        for (int rr = 0; rr < 2; rr++) {
            int n = nodeBase + warp_m * 32 + mt * 16 + grp + rr * 8;
            if (n >= NN) n = NN - 1;
            float c0 = (float)__ldg(&g_cnt[n]);
            float c1 = (float)__ldg(&g_cnt[NN + n]);
            float c2 = (float)__ldg(&g_cnt[2 * NN + n]);
            float inv = 1.0f / fmaxf(c0 + c1 + c2, 1.0f);
#pragma unroll
            for (int t = 0; t < 8; t++) {
#pragma unroll
                for (int q = 0; q < 2; q++) {
                    int col = warp_n * 64 + t * 8 + 2 * tid4 + q;
                    int ci = rr * 2 + q;
                    float v = acc[mt][t][ci] + c0 * __ldg(&b3[col])
                            + c1 * __ldg(&b3[DD + col]) + c2 * __ldg(&b3[2 * DD + col]);
                    acc[mt][t][ci] = fmaxf(v * inv, 0.0f);
                }
            }
        }
    }

    // ================= phase 2: K = 128 self loop =================
    for (int c = 0; c < 4; c++) {
        int d0 = c * 32;
#pragma unroll
        for (int t = 0; t < 4; t++) {
            int idx = tid + t * 256;
            int nl = idx >> 3, c4 = idx & 7;
            int n = nodeBase + nl; if (n >= NN) n = NN - 1;
            float4 v = __ldg((const float4*)(X + (size_t)n * DD + d0) + c4);
            int kk = c4 * 4;
            As[(kk + 0) * ASTR + nl] = to_tf32(v.x);
            As[(kk + 1) * ASTR + nl] = to_tf32(v.y);
            As[(kk + 2) * ASTR + nl] = to_tf32(v.z);
            As[(kk + 3) * ASTR + nl] = to_tf32(v.w);
        }
#pragma unroll
        for (int t = 0; t < 4; t++) {
            int idx = tid + t * 256;
            int k = idx >> 5, o4 = idx & 31;
            float4 v = __ldg((const float4*)(Wst + (d0 + k) * DD) + o4);
            *(float4*)&Bs[k * BSTR + o4 * 4] = v;
        }
        __syncthreads();
#pragma unroll
        for (int ks = 0; ks < 4; ks++) {
            int k0 = ks * 8;
            unsigned a[2][4];
#pragma unroll
            for (int mt = 0; mt < 2; mt++) {
                int mrow = warp_m * 32 + mt * 16 + grp;
                a[mt][0] = __float_as_uint(As[(k0 + tid4) * ASTR + mrow]);
                a[mt][1] = __float_as_uint(As[(k0 + tid4) * ASTR + mrow + 8]);
                a[mt][2] = __float_as_uint(As[(k0 + tid4 + 4) * ASTR + mrow]);
                a[mt][3] = __float_as_uint(As[(k0 + tid4 + 4) * ASTR + mrow + 8]);
            }
#pragma unroll
            for (int t = 0; t < 8; t++) {
                int oc = warp_n * 64 + t * 8 + grp;
                unsigned b0 = __float_as_uint(Bs[(k0 + tid4) * BSTR + oc]);
                unsigned b1 = __float_as_uint(Bs[(k0 + tid4 + 4) * BSTR + oc]);
                mma_tf32(acc[0][t], a[0], b0, b1);
                mma_tf32(acc[1][t], a[1], b0, b1);
            }
        }
        __syncthreads();
    }

    // ---------- final epilogue: +bs, LayerNorm over 128 outs ----------
    float ps[2][2], ps2[2][2];
#pragma unroll
    for (int mt = 0; mt < 2; mt++) {
#pragma unroll
        for (int rr = 0; rr < 2; rr++) {
            float s = 0.f, s2 = 0.f;
#pragma unroll
            for (int t = 0; t < 8; t++) {
#pragma unroll
                for (int q = 0; q < 2; q++) {
                    int col = warp_n * 64 + t * 8 + 2 * tid4 + q;
                    int ci = rr * 2 + q;
                    float v = acc[mt][t][ci] + __ldg(&bs[col]);
                    acc[mt][t][ci] = v;
                    s += v; s2 += v * v;
                }
            }
            // reduce across the 4 tid4 lanes (grp preserved)
            s  += __shfl_xor_sync(0xffffffffu, s, 1);
            s2 += __shfl_xor_sync(0xffffffffu, s2, 1);
            s  += __shfl_xor_sync(0xffffffffu, s, 2);
            s2 += __shfl_xor_sync(0xffffffffu, s2, 2);
            ps[mt][rr] = s; ps2[mt][rr] = s2;
            if (tid4 == 0) {
                int ln = warp_m * 32 + mt * 16 + grp + rr * 8;
                Sred[warp_n][ln][0] = s;
                Sred[warp_n][ln][1] = s2;
            }
        }
    }
    __syncthreads();
#pragma unroll
    for (int mt = 0; mt < 2; mt++) {
#pragma unroll
        for (int rr = 0; rr < 2; rr++) {
            int ln = warp_m * 32 + mt * 16 + grp + rr * 8;
            float s  = ps[mt][rr]  + Sred[1 - warp_n][ln][0];
            float s2 = ps2[mt][rr] + Sred[1 - warp_n][ln][1];
            float mean = s * (1.0f / 128.0f);
            float var  = s2 * (1.0f / 128.0f) - mean * mean;
            float rstd = rsqrtf(var + LN_EPS);
            int n = nodeBase + ln;
            if (n < NN) {
#pragma unroll
                for (int t = 0; t < 8; t++) {
                    int col = warp_n * 64 + t * 8 + 2 * tid4;
                    float2 o;
                    o.x = (acc[mt][t][rr * 2 + 0] - mean) * rstd * __ldg(&gamma[col]) + __ldg(&beta[col]);
                    o.y = (acc[mt][t][rr * 2 + 1] - mean) * rstd * __ldg(&gamma[col + 1]) + __ldg(&beta[col + 1]);
                    *(float2*)(outp + (size_t)n * DD + col) = o;
                }
            }
        }
    }
}

// ---- zero counters (tiny) ----
__global__ void zero_cnt_kernel() {
    int idx = blockIdx.x * blockDim.x + threadIdx.x;
    if (idx < TN) g_cnt[idx] = 0;
}

extern "C" void kernel_launch(void* const* d_in, const int* in_sizes, int n_in,
                              void* d_out, int out_size) {
    const int*   edges    = (const int*)d_in[0];
    const float* node_emb = (const float*)d_in[1];
    const float* W1  = (const float*)d_in[2];
    const float* b1  = (const float*)d_in[3];
    const float* Ws1 = (const float*)d_in[4];
    const float* bs1 = (const float*)d_in[5];
    const float* g1  = (const float*)d_in[6];
    const float* be1 = (const float*)d_in[7];
    const float* W2  = (const float*)d_in[8];
    const float* b2  = (const float*)d_in[9];
    const float* Ws2 = (const float*)d_in[10];
    const float* bs2 = (const float*)d_in[11];
    const float* g2  = (const float*)d_in[12];
    const float* be2 = (const float*)d_in[13];
    float* out = (float*)d_out;

    transpose_w_kernel<<<(8 * DD * DD + 255) / 256, 256>>>(W1, Ws1, W2, Ws2);
    zero_cnt_kernel<<<(TN + 255) / 256, 256>>>();
    count_kernel<<<(EE + 255) / 256, 256>>>(edges);
    scan1_kernel<<<NBLK, 256>>>();
    scan2_kernel<<<1, 128>>>();
    scan3_kernel<<<(TN + 255) / 256, 256>>>();
    fill_kernel<<<(EE + 255) / 256, 256>>>(edges);
    gather_kernel<<<(TN * 32 + 255) / 256, 256>>>(node_emb, 0);
    transform_kernel<<<(NN + 127) / 128, 256>>>(node_emb, out, b1, bs1, g1, be1, 0);
    gather_kernel<<<(TN * 32 + 255) / 256, 256>>>(node_emb, 1);
    transform_kernel<<<(NN + 127) / 128, 256>>>(node_emb, out, b2, bs2, g2, be2, 1);
}

// round 5
// speedup vs baseline: 3.2186x; 1.7515x over previous
#include <cuda_runtime.h>
#include <cuda_fp16.h>

#define NN 100000
#define EE 1600000
#define TN (3 * NN)
#define DD 128
#define D2 64             // half2 per row
#define RR 400
#define LN_EPS 1e-5f
#define ASTR2 137         // As smem stride in half2 words
#define BSTR2 136         // Bs smem stride in half2 words (mult of 4; 8 mod 32 => conflict-free mma loads)
#define SCAN_BLK 4096
#define NBLK ((TN + SCAN_BLK - 1) / SCAN_BLK)   // 74

// ---- scratch (static device globals; no allocations allowed) ----
__device__ unsigned g_aggu[(size_t)TN * D2];    // aggregated features, half2-packed
__device__ unsigned g_xu[(size_t)NN * D2];      // node_emb as half2
__device__ unsigned g_x1u[(size_t)NN * D2];     // layer-1 output as half2
__device__ int      g_cnt[TN];
__device__ int      g_rowptr[TN];
__device__ int      g_cur[TN];
__device__ int      g_blk[128];
__device__ int      g_eidx[EE];
__device__ unsigned g_Wtu[2][3 * D2 * DD];      // relation weights, k-pair-major half2: [d2][o]
__device__ unsigned g_Wstu[2][D2 * DD];         // self weights, same layout

__device__ __forceinline__ unsigned pack_h2(float a, float b) {
    __half2 h = __floats2half2_rn(a, b);
    return *reinterpret_cast<unsigned*>(&h);
}
__device__ __forceinline__ float2 unpack_h2(unsigned u) {
    return __half22float2(*reinterpret_cast<__half2*>(&u));
}

__device__ __forceinline__ void mma_f16(float* c, const unsigned* a, unsigned b0, unsigned b1) {
    asm volatile(
        "mma.sync.aligned.m16n8k16.row.col.f32.f16.f16.f32 "
        "{%0,%1,%2,%3},{%4,%5,%6,%7},{%8,%9},{%0,%1,%2,%3};\n"
        : "+f"(c[0]), "+f"(c[1]), "+f"(c[2]), "+f"(c[3])
        : "r"(a[0]), "r"(a[1]), "r"(a[2]), "r"(a[3]), "r"(b0), "r"(b1));
}

// ---- pack weights to k-pair-major half2 ----
__global__ void pack_w_kernel(const float* __restrict__ W1, const float* __restrict__ Ws1,
                              const float* __restrict__ W2, const float* __restrict__ Ws2) {
    int idx = blockIdx.x * blockDim.x + threadIdx.x;   // 8 matrices * 8192
    if (idx >= 8 * D2 * DD) return;
    int m = idx >> 13;
    int e = idx & (D2 * DD - 1);
    int d2 = e >> 7;          // k-pair index 0..63
    int o = e & 127;
    const float* src;
    unsigned* dst;
    if (m < 3)       { src = W1 + m * DD * DD;       dst = g_Wtu[0] + m * D2 * DD; }
    else if (m == 3) { src = Ws1;                    dst = g_Wstu[0]; }
    else if (m < 7)  { src = W2 + (m - 4) * DD * DD; dst = g_Wtu[1] + (m - 4) * D2 * DD; }
    else             { src = Ws2;                    dst = g_Wstu[1]; }
    dst[d2 * DD + o] = pack_h2(src[o * DD + 2 * d2], src[o * DD + 2 * d2 + 1]);
}

// ---- convert node_emb to half2 ----
__global__ void xconvert_kernel(const float* __restrict__ x) {
    int i = blockIdx.x * blockDim.x + threadIdx.x;     // NN*D2/2 uint2 stores
    if (i >= NN * D2 / 2) return;
    float4 v = __ldg((const float4*)x + i);
    uint2 o;
    o.x = pack_h2(v.x, v.y);
    o.y = pack_h2(v.z, v.w);
    ((uint2*)g_xu)[i] = o;
}

// ---- per-(bucket,dst) in-degree counts ----
__global__ void count_kernel(const int* __restrict__ edges) {
    int e = blockIdx.x * blockDim.x + threadIdx.x;
    if (e >= EE) return;
    int rel = edges[3 * e + 1];
    int dst = edges[3 * e + 2];
    int b = (rel >= RR) + (rel >= 2 * RR);
    atomicAdd(&g_cnt[b * NN + dst], 1);
}

// ---- exclusive scan pass 1 ----
__global__ __launch_bounds__(256) void scan1_kernel() {
    __shared__ int sm[256];
    int tid = threadIdx.x;
    int base = blockIdx.x * SCAN_BLK + tid * 16;
    int c[16];
    int run = 0;
#pragma unroll
    for (int t = 0; t < 16; t++) {
        int v = (base + t < TN) ? g_cnt[base + t] : 0;
        c[t] = run;
        run += v;
    }
    sm[tid] = run;
    __syncthreads();
    for (int d = 1; d < 256; d <<= 1) {
        int v = (tid >= d) ? sm[tid - d] : 0;
        __syncthreads();
        sm[tid] += v;
        __syncthreads();
    }
    int texcl = sm[tid] - run;
#pragma unroll
    for (int t = 0; t < 16; t++)
        if (base + t < TN) g_rowptr[base + t] = texcl + c[t];
    if (tid == 255) g_blk[blockIdx.x] = sm[255];
}

// ---- scan pass 2 ----
__global__ __launch_bounds__(128) void scan2_kernel() {
    __shared__ int sm[128];
    int tid = threadIdx.x;
    int v = (tid < NBLK) ? g_blk[tid] : 0;
    sm[tid] = v;
    __syncthreads();
    for (int d = 1; d < 128; d <<= 1) {
        int u = (tid >= d) ? sm[tid - d] : 0;
        __syncthreads();
        sm[tid] += u;
        __syncthreads();
    }
    if (tid < NBLK) g_blk[tid] = sm[tid] - v;
}

// ---- scan pass 3 ----
__global__ void scan3_kernel() {
    int idx = blockIdx.x * blockDim.x + threadIdx.x;
    if (idx >= TN) return;
    int v = g_rowptr[idx] + g_blk[idx / SCAN_BLK];
    g_rowptr[idx] = v;
    g_cur[idx] = v;
}

// ---- fill CSR ----
__global__ void fill_kernel(const int* __restrict__ edges) {
    int e = blockIdx.x * blockDim.x + threadIdx.x;
    if (e >= EE) return;
    int src = edges[3 * e + 0];
    int rel = edges[3 * e + 1];
    int dst = edges[3 * e + 2];
    int b = (rel >= RR) + (rel >= 2 * RR);
    int pos = atomicAdd(&g_cur[b * NN + dst], 1);
    g_eidx[pos] = src;
}

// ---- gather: warp per segment; half2 rows, fp32 accumulate, half2 store ----
__global__ void gather_kernel(int layer) {
    int gw = (blockIdx.x * blockDim.x + threadIdx.x) >> 5;
    int lane = threadIdx.x & 31;
    if (gw >= TN) return;
    const unsigned* X = layer ? g_x1u : g_xu;
    int s = __ldg(&g_rowptr[gw]);
    int e = (gw + 1 < TN) ? __ldg(&g_rowptr[gw + 1]) : EE;
    float a0 = 0.f, a1 = 0.f, a2 = 0.f, a3 = 0.f;
    float b0 = 0.f, b1 = 0.f, b2 = 0.f, b3 = 0.f;
    int j = s;
    for (; j + 2 <= e; j += 2) {
        int s0 = __ldg(&g_eidx[j]);
        int s1 = __ldg(&g_eidx[j + 1]);
        uint2 w0 = __ldg((const uint2*)(X + (size_t)s0 * D2) + lane);
        uint2 w1 = __ldg((const uint2*)(X + (size_t)s1 * D2) + lane);
        float2 f0 = unpack_h2(w0.x), f1 = unpack_h2(w0.y);
        float2 f2 = unpack_h2(w1.x), f3 = unpack_h2(w1.y);
        a0 += f0.x; a1 += f0.y; a2 += f1.x; a3 += f1.y;
        b0 += f2.x; b1 += f2.y; b2 += f3.x; b3 += f3.y;
    }
    if (j < e) {
        int s0 = __ldg(&g_eidx[j]);
        uint2 w0 = __ldg((const uint2*)(X + (size_t)s0 * D2) + lane);
        float2 f0 = unpack_h2(w0.x), f1 = unpack_h2(w0.y);
        a0 += f0.x; a1 += f0.y; a2 += f1.x; a3 += f1.y;
    }
    uint2 st;
    st.x = pack_h2(a0 + b0, a1 + b1);
    st.y = pack_h2(a2 + b2, a3 + b3);
    ((uint2*)(g_aggu + (size_t)gw * D2))[lane] = st;
}

// ---- fused transform on fp16 tensor cores (mma m16n8k16, fp32 accum):
//      relation GEMM (K=384) -> relu((.+cnt*b)/deg) -> self GEMM (K=128)
//      -> +bs -> LayerNorm.  CTA: 256 threads, 128 nodes x 128 outs. ----
__global__ __launch_bounds__(256) void transform_kernel(
    float* __restrict__ Out,
    const float* __restrict__ b3,    // (3,128)
    const float* __restrict__ bs,    // (128)
    const float* __restrict__ gamma, // (128)
    const float* __restrict__ beta,  // (128)
    int layer) {
    __shared__ unsigned As2[16 * ASTR2];             // [k2][node] half2-packed
    __shared__ __align__(16) unsigned Bs2[16 * BSTR2]; // [k2][out]
    __shared__ float Sred[2][128][2];

    const unsigned* Xh  = layer ? g_x1u : g_xu;
    const unsigned* Wt  = g_Wtu[layer];
    const unsigned* Wst = g_Wstu[layer];

    const int tid = threadIdx.x;
    const int lane = tid & 31;
    const int wid = tid >> 5;
    const int warp_m = wid & 3;
    const int warp_n = wid >> 2;
    const int grp = lane >> 2;
    const int tid4 = lane & 3;
    const int nodeBase = blockIdx.x * 128;

    float acc[2][8][4];
#pragma unroll
    for (int mt = 0; mt < 2; mt++)
#pragma unroll
        for (int t = 0; t < 8; t++)
#pragma unroll
            for (int q = 0; q < 4; q++) acc[mt][t][q] = 0.f;

    // ================= phase 1: K = 384 over agg =================
    for (int c = 0; c < 12; c++) {
        int r = c >> 2;
        int d20 = (c & 3) * 16;                   // half2 offset within row
        const unsigned* Ap = g_aggu + (size_t)r * NN * D2;
        const unsigned* Bp = Wt + r * D2 * DD;
        // A: 128 nodes x 16 half2 -> As2[k2][node]; 512 uint4 loads
#pragma unroll
        for (int t = 0; t < 2; t++) {
            int idx = tid + t * 256;              // 0..511
            int nl = idx >> 2, c4 = idx & 3;
            int n = nodeBase + nl; if (n >= NN) n = NN - 1;
            uint4 v = __ldg((const uint4*)(Ap + (size_t)n * D2 + d20) + c4);
            int kk = c4 * 4;
            As2[(kk + 0) * ASTR2 + nl] = v.x;
            As2[(kk + 1) * ASTR2 + nl] = v.y;
            As2[(kk + 2) * ASTR2 + nl] = v.z;
            As2[(kk + 3) * ASTR2 + nl] = v.w;
        }
        // B: 16 k2 x 128 outs; 512 uint4 loads (4 consecutive o)
#pragma unroll
        for (int t = 0; t < 2; t++) {
            int idx = tid + t * 256;
            int k2 = idx >> 5, o4 = idx & 31;
            uint4 v = __ldg((const uint4*)(Bp + (d20 + k2) * DD) + o4);
            *(uint4*)&Bs2[k2 * BSTR2 + o4 * 4] = v;
        }
        __syncthreads();
#pragma unroll
        for (int ks = 0; ks < 2; ks++) {
            int k20 = ks * 8;
            unsigned a[2][4];
#pragma unroll
            for (int mt = 0; mt < 2; mt++) {
                int mrow = warp_m * 32 + mt * 16 + grp;
                a[mt][0] = As2[(k20 + tid4) * ASTR2 + mrow];
                a[mt][1] = As2[(k20 + tid4) * ASTR2 + mrow + 8];
                a[mt][2] = As2[(k20 + tid4 + 4) * ASTR2 + mrow];
                a[mt][3] = As2[(k20 + tid4 + 4) * ASTR2 + mrow + 8];
            }
#pragma unroll
            for (int t = 0; t < 8; t++) {
                int oc = warp_n * 64 + t * 8 + grp;
                unsigned b0 = Bs2[(k20 + tid4) * BSTR2 + oc];
                unsigned b1 = Bs2[(k20 + tid4 + 4) * BSTR2 + oc];
                mma_f16(acc[0][t], a[0], b0, b1);
                mma_f16(acc[1][t], a[1], b0, b1);
            }
        }
        __syncthreads();
    }

    // ---------- mid epilogue: +cnt*bias, /degree, relu ----------
#pragma unroll
    for (int mt = 0; mt < 2; mt++) {
#pragma unroll
        for (int rr = 0; rr < 2; rr++) {
            int n = nodeBase + warp_m * 32 + mt * 16 + grp + rr * 8;
            if (n >= NN) n = NN - 1;
            float c0 = (float)__ldg(&g_cnt[n]);
            float c1 = (float)__ldg(&g_cnt[NN + n]);
            float c2 = (float)__ldg(&g_cnt[2 * NN + n]);
            float inv = 1.0f / fmaxf(c0 + c1 + c2, 1.0f);
#pragma unroll
            for (int t = 0; t < 8; t++) {
#pragma unroll
                for (int q = 0; q < 2; q++) {
                    int col = warp_n * 64 + t * 8 + 2 * tid4 + q;
                    int ci = rr * 2 + q;
                    float v = acc[mt][t][ci] + c0 * __ldg(&b3[col])
                            + c1 * __ldg(&b3[DD + col]) + c2 * __ldg(&b3[2 * DD + col]);
                    acc[mt][t][ci] = fmaxf(v * inv, 0.0f);
                }
            }
        }
    }

    // ================= phase 2: K = 128 self loop =================
    for (int c = 0; c < 4; c++) {
        int d20 = c * 16;
#pragma unroll
        for (int t = 0; t < 2; t++) {
            int idx = tid + t * 256;
            int nl = idx >> 2, c4 = idx & 3;
            int n = nodeBase + nl; if (n >= NN) n = NN - 1;
            uint4 v = __ldg((const uint4*)(Xh + (size_t)n * D2 + d20) + c4);
            int kk = c4 * 4;
            As2[(kk + 0) * ASTR2 + nl] = v.x;
            As2[(kk + 1) * ASTR2 + nl] = v.y;
            As2[(kk + 2) * ASTR2 + nl] = v.z;
            As2[(kk + 3) * ASTR2 + nl] = v.w;
        }
#pragma unroll
        for (int t = 0; t < 2; t++) {
            int idx = tid + t * 256;
            int k2 = idx >> 5, o4 = idx & 31;
            uint4 v = __ldg((const uint4*)(Wst + (d20 + k2) * DD) + o4);
            *(uint4*)&Bs2[k2 * BSTR2 + o4 * 4] = v;
        }
        __syncthreads();
#pragma unroll
        for (int ks = 0; ks < 2; ks++) {
            int k20 = ks * 8;
            unsigned a[2][4];
#pragma unroll
            for (int mt = 0; mt < 2; mt++) {
                int mrow = warp_m * 32 + mt * 16 + grp;
                a[mt][0] = As2[(k20 + tid4) * ASTR2 + mrow];
                a[mt][1] = As2[(k20 + tid4) * ASTR2 + mrow + 8];
                a[mt][2] = As2[(k20 + tid4 + 4) * ASTR2 + mrow];
                a[mt][3] = As2[(k20 + tid4 + 4) * ASTR2 + mrow + 8];
            }
#pragma unroll
            for (int t = 0; t < 8; t++) {
                int oc = warp_n * 64 + t * 8 + grp;
                unsigned b0 = Bs2[(k20 + tid4) * BSTR2 + oc];
                unsigned b1 = Bs2[(k20 + tid4 + 4) * BSTR2 + oc];
                mma_f16(acc[0][t], a[0], b0, b1);
                mma_f16(acc[1][t], a[1], b0, b1);
            }
        }
        __syncthreads();
    }

    // ---------- final epilogue: +bs, LayerNorm over 128 outs ----------
    float ps[2][2], ps2[2][2];
#pragma unroll
    for (int mt = 0; mt < 2; mt++) {
#pragma unroll
        for (int rr = 0; rr < 2; rr++) {
            float s = 0.f, s2 = 0.f;
#pragma unroll
            for (int t = 0; t < 8; t++) {
#pragma unroll
                for (int q = 0; q < 2; q++) {
                    int col = warp_n * 64 + t * 8 + 2 * tid4 + q;
                    int ci = rr * 2 + q;
                    float v = acc[mt][t][ci] + __ldg(&bs[col]);
                    acc[mt][t][ci] = v;
                    s += v; s2 += v * v;
                }
            }
            s  += __shfl_xor_sync(0xffffffffu, s, 1);
            s2 += __shfl_xor_sync(0xffffffffu, s2, 1);
            s  += __shfl_xor_sync(0xffffffffu, s, 2);
            s2 += __shfl_xor_sync(0xffffffffu, s2, 2);
            ps[mt][rr] = s; ps2[mt][rr] = s2;
            if (tid4 == 0) {
                int ln = warp_m * 32 + mt * 16 + grp + rr * 8;
                Sred[warp_n][ln][0] = s;
                Sred[warp_n][ln][1] = s2;
            }
        }
    }
    __syncthreads();
#pragma unroll
    for (int mt = 0; mt < 2; mt++) {
#pragma unroll
        for (int rr = 0; rr < 2; rr++) {
            int ln = warp_m * 32 + mt * 16 + grp + rr * 8;
            float s  = ps[mt][rr]  + Sred[1 - warp_n][ln][0];
            float s2 = ps2[mt][rr] + Sred[1 - warp_n][ln][1];
            float mean = s * (1.0f / 128.0f);
            float var  = s2 * (1.0f / 128.0f) - mean * mean;
            float rstd = rsqrtf(var + LN_EPS);
            int n = nodeBase + ln;
            if (n < NN) {
#pragma unroll
                for (int t = 0; t < 8; t++) {
                    int col = warp_n * 64 + t * 8 + 2 * tid4;
                    float ox = (acc[mt][t][rr * 2 + 0] - mean) * rstd * __ldg(&gamma[col]) + __ldg(&beta[col]);
                    float oy = (acc[mt][t][rr * 2 + 1] - mean) * rstd * __ldg(&gamma[col + 1]) + __ldg(&beta[col + 1]);
                    if (layer == 0) {
                        g_x1u[(size_t)n * D2 + (col >> 1)] = pack_h2(ox, oy);
                    } else {
                        float2 o = make_float2(ox, oy);
                        *(float2*)(Out + (size_t)n * DD + col) = o;
                    }
                }
            }
        }
    }
}

// ---- zero counters (tiny) ----
__global__ void zero_cnt_kernel() {
    int idx = blockIdx.x * blockDim.x + threadIdx.x;
    if (idx < TN) g_cnt[idx] = 0;
}

extern "C" void kernel_launch(void* const* d_in, const int* in_sizes, int n_in,
                              void* d_out, int out_size) {
    const int*   edges    = (const int*)d_in[0];
    const float* node_emb = (const float*)d_in[1];
    const float* W1  = (const float*)d_in[2];
    const float* b1  = (const float*)d_in[3];
    const float* Ws1 = (const float*)d_in[4];
    const float* bs1 = (const float*)d_in[5];
    const float* g1  = (const float*)d_in[6];
    const float* be1 = (const float*)d_in[7];
    const float* W2  = (const float*)d_in[8];
    const float* b2  = (const float*)d_in[9];
    const float* Ws2 = (const float*)d_in[10];
    const float* bs2 = (const float*)d_in[11];
    const float* g2  = (const float*)d_in[12];
    const float* be2 = (const float*)d_in[13];
    float* out = (float*)d_out;

    pack_w_kernel<<<(8 * D2 * DD + 255) / 256, 256>>>(W1, Ws1, W2, Ws2);
    xconvert_kernel<<<(NN * D2 / 2 + 255) / 256, 256>>>(node_emb);
    zero_cnt_kernel<<<(TN + 255) / 256, 256>>>();
    count_kernel<<<(EE + 255) / 256, 256>>>(edges);
    scan1_kernel<<<NBLK, 256>>>();
    scan2_kernel<<<1, 128>>>();
    scan3_kernel<<<(TN + 255) / 256, 256>>>();
    fill_kernel<<<(EE + 255) / 256, 256>>>(edges);
    gather_kernel<<<(TN * 32 + 255) / 256, 256>>>(0);
    transform_kernel<<<(NN + 127) / 128, 256>>>(out, b1, bs1, g1, be1, 0);
    gather_kernel<<<(TN * 32 + 255) / 256, 256>>>(1);
    transform_kernel<<<(NN + 127) / 128, 256>>>(out, b2, bs2, g2, be2, 1);
}